// round 6
// baseline (speedup 1.0000x reference)
#include <cuda_runtime.h>
#include <math.h>

// Problem constants: x is (64, 128, 10000) fp32.
#define BATCH 64
#define CH    128
#define T_LEN 10000
#define TT    128          // time-chunk per stats block
#define T4    (T_LEN / 4)  // 2500
#define NWARP 16           // warps per stats block

// Scratch (no allocations allowed). Statically zero-initialized.
__device__ float g_m[BATCH * T_LEN];      // mean over channels at each (b,t)
__device__ float g_sum [BATCH * CH];      // sum of y over time (accumulator)
__device__ float g_sum2[BATCH * CH];      // sum of y^2 over time (accumulator)
__device__ float g_mean[BATCH * CH];
__device__ float g_istd[BATCH * CH];

// ---------------------------------------------------------------- kernel 1: stats (register-resident)
// Block = (b, t-chunk of 128), 512 threads = 16 warps, ~8.7 KB smem -> 2 blocks/SM (reg-bound).
// Warp w owns channels [w*8, w*8+8); lane l owns the float4 at t=4l.
// Phase 1: 8 LDG.128 kept in registers; float4 colsum -> smem partials.
// Combine: 128 threads reduce 16 partials -> channel mean mrow; write g_m.
// Phase 2: per-channel (y, y^2) from registers via warp shuffle reduction. No smem tile.
__global__ __launch_bounds__(512, 2) void eeg_stats_kernel(const float* __restrict__ x) {
    __shared__ float part[NWARP * TT];     // per-warp colsum partials
    __shared__ float mrow[TT];             // channel mean per t

    const int b    = blockIdx.y;
    const int t0   = blockIdx.x * TT;
    const int tid  = threadIdx.x;
    const int lane = tid & 31;
    const int w    = tid >> 5;             // warp 0..15
    const int t    = 4 * lane;             // float4 t-position within chunk
    const int vlen = min(TT, T_LEN - t0);  // 128, or 16 on the tail chunk
    const bool valid = t < vlen;
    const int cbase = w * 8;

    const float* __restrict__ xp =
        x + (size_t)b * CH * T_LEN + (size_t)cbase * T_LEN + t0 + t;

    // Phase 1: load 8 channel rows into registers; accumulate float4 colsum.
    float4 v[8];
    float4 csum = make_float4(0.f, 0.f, 0.f, 0.f);
    #pragma unroll
    for (int c = 0; c < 8; ++c) {
        v[c] = valid ? *reinterpret_cast<const float4*>(xp + (size_t)c * T_LEN)
                     : make_float4(0.f, 0.f, 0.f, 0.f);
        csum.x += v[c].x; csum.y += v[c].y; csum.z += v[c].z; csum.w += v[c].w;
    }
    *reinterpret_cast<float4*>(&part[w * TT + t]) = csum;
    __syncthreads();

    // Combine 16 warp partials -> channel mean m[t]; write g_m. (first 128 threads)
    if (tid < TT) {
        float m = 0.f;
        #pragma unroll
        for (int w2 = 0; w2 < NWARP; ++w2) m += part[w2 * TT + tid];
        m *= (1.0f / 128.0f);
        mrow[tid] = m;
        if (tid < vlen) g_m[(size_t)b * T_LEN + t0 + tid] = m;
    }
    __syncthreads();

    // Phase 2: per-channel sums from registers. For channel cbase+c, the 32 lanes of
    // warp w cover all 128 t of this chunk -> warp reduction, lane 0 does the atomic.
    // (mrow is 0 beyond vlen, v is 0 for invalid lanes, so padding contributes 0.)
    float4 m4 = *reinterpret_cast<const float4*>(&mrow[t]);   // conflict-free LDS.128
    #pragma unroll
    for (int c = 0; c < 8; ++c) {
        float a0 = v[c].x - m4.x, a1 = v[c].y - m4.y;
        float a2 = v[c].z - m4.z, a3 = v[c].w - m4.w;
        float sy  = (a0 + a1) + (a2 + a3);
        float sy2 = a0 * a0 + a1 * a1 + a2 * a2 + a3 * a3;
        #pragma unroll
        for (int off = 16; off > 0; off >>= 1) {
            sy  += __shfl_xor_sync(0xffffffffu, sy,  off);
            sy2 += __shfl_xor_sync(0xffffffffu, sy2, off);
        }
        if (lane == 0) {
            atomicAdd(&g_sum [b * CH + cbase + c], sy);
            atomicAdd(&g_sum2[b * CH + cbase + c], sy2);
        }
    }
}

// ---------------------------------------------------------------- kernel 2: finalize + re-zero
__global__ void eeg_finalize_kernel() {
    int i = blockIdx.x * blockDim.x + threadIdx.x;
    if (i < BATCH * CH) {
        const float inv_t = 1.0f / (float)T_LEN;
        float mean = g_sum[i] * inv_t;
        float var  = g_sum2[i] * inv_t - mean * mean;
        float sd   = sqrtf(fmaxf(var, 0.f));
        g_mean[i] = mean;
        g_istd[i] = (sd == 0.f) ? 1.f : (1.f / sd);
        g_sum [i] = 0.f;       // reset for next graph replay (statically zero-init)
        g_sum2[i] = 0.f;
    }
}

// ---------------------------------------------------------------- kernel 3: normalize
// grid = (5, 8192): blockIdx.y = (b,c) pair. 2 float4 per thread, loads front-batched.
__global__ __launch_bounds__(256) void eeg_norm_kernel(const float4* __restrict__ x4,
                                                       float4* __restrict__ o4) {
    const int bc = blockIdx.y;
    const int b  = bc >> 7;
    const int ta = blockIdx.x * 512 + threadIdx.x;
    const int tb = ta + 256;

    const float mean = g_mean[bc];
    const float istd = g_istd[bc];

    const float4* __restrict__ xp = x4 + (size_t)bc * T4;
    float4*                   op = o4 + (size_t)bc * T4;
    const float4* __restrict__ mp =
        reinterpret_cast<const float4*>(g_m + (size_t)b * T_LEN);

    const bool va = ta < T4;
    const bool vb = tb < T4;

    float4 v0, v1, m0, m1;
    if (va) { v0 = xp[ta]; m0 = mp[ta]; }
    if (vb) { v1 = xp[tb]; m1 = mp[tb]; }

    if (va) {
        float4 r;
        r.x = (v0.x - m0.x - mean) * istd;
        r.y = (v0.y - m0.y - mean) * istd;
        r.z = (v0.z - m0.z - mean) * istd;
        r.w = (v0.w - m0.w - mean) * istd;
        op[ta] = r;
    }
    if (vb) {
        float4 r;
        r.x = (v1.x - m1.x - mean) * istd;
        r.y = (v1.y - m1.y - mean) * istd;
        r.z = (v1.z - m1.z - mean) * istd;
        r.w = (v1.w - m1.w - mean) * istd;
        op[tb] = r;
    }
}

// ---------------------------------------------------------------- launch
extern "C" void kernel_launch(void* const* d_in, const int* in_sizes, int n_in,
                              void* d_out, int out_size) {
    (void)in_sizes; (void)n_in; (void)out_size;
    const float* x = (const float*)d_in[0];
    float* out = (float*)d_out;

    // 1) stats (accumulators start zeroed; finalize re-zeroes them)
    dim3 sgrid((T_LEN + TT - 1) / TT, BATCH);    // (79, 64)
    eeg_stats_kernel<<<sgrid, 512>>>(x);

    // 2) finalize mean / inv_std + reset accumulators
    eeg_finalize_kernel<<<(BATCH * CH + 255) / 256, 256>>>();

    // 3) normalize
    dim3 ngrid((T4 + 511) / 512, BATCH * CH);    // (5, 8192)
    eeg_norm_kernel<<<ngrid, 256>>>((const float4*)x, (float4*)out);
}

// round 9
// speedup vs baseline: 1.1482x; 1.1482x over previous
#include <cuda_runtime.h>
#include <cstdint>
#include <math.h>

// Problem constants: x is (64, 128, 10000) fp32.
#define BATCH 64
#define CH    128
#define T_LEN 10000
#define TT    64            // time-chunk per pipeline stage
#define PITCH 68            // floats; 272B rows: 16B-aligned for LDGSTS, ≡4 mod 32 banks
#define NCHUNK 157          // ceil(10000/64); last chunk vlen=16
#define GSTRIDE 6           // chunk stride -> grid (6,64) = 384 blocks
#define T4    (T_LEN / 4)   // 2500

// Scratch (no allocations allowed). Statically zero-initialized.
__device__ float g_m[BATCH * T_LEN];      // mean over channels at each (b,t)
__device__ float g_sum [BATCH * CH];      // accumulator (reset by finalize)
__device__ float g_sum2[BATCH * CH];      // accumulator (reset by finalize)
__device__ float g_mean[BATCH * CH];
__device__ float g_istd[BATCH * CH];

__device__ __forceinline__ void cp_async16(unsigned sdst, const void* gsrc) {
    asm volatile("cp.async.cg.shared.global [%0], [%1], 16;\n"
                 :: "r"(sdst), "l"(gsrc));
}
__device__ __forceinline__ void cp_commit() {
    asm volatile("cp.async.commit_group;\n");
}
template <int N>
__device__ __forceinline__ void cp_wait() {
    asm volatile("cp.async.wait_group %0;\n" :: "n"(N));
}

// ---------------------------------------------------------------- kernel 1: pipelined stats
// 256 threads. Issues chunk k+1 via cp.async while computing chunk k from smem.
// Per-thread (c,h) channel-stat accumulators live in registers across chunks;
// one atomicAdd pair per thread at the end.
__global__ __launch_bounds__(256) void eeg_stats_kernel(const float* __restrict__ x) {
    extern __shared__ float s[];
    float* tile0 = s;                          // CH*PITCH
    float* tile1 = s + CH * PITCH;             // CH*PITCH
    float* part  = s + 2 * CH * PITCH;         // 4 * TT
    float* mrow  = part + 4 * TT;              // TT

    const int b   = blockIdx.y;
    const int tid = threadIdx.x;

    // cp.async issue mapping: 8 rows-of-16 passes; thread covers (row, 16B t-slot)
    const int lrow = tid >> 4;                 // 0..15
    const int lt4  = tid & 15;                 // float4 slot 0..15 (t = 4*lt4)
    // colsum mapping
    const int cs_t = tid & 63;                 // time
    const int cs_g = tid >> 6;                 // channel group 0..3
    // phase-2 mapping (fixed per thread across all chunks)
    const int p2_c = tid & (CH - 1);
    const int p2_h = tid >> 7;                 // 0..1 -> t base h*32

    const float* __restrict__ xb = x + (size_t)b * CH * T_LEN;

    unsigned s0 = (unsigned)__cvta_generic_to_shared(tile0);
    unsigned s1 = (unsigned)__cvta_generic_to_shared(tile1);

    float acc_sy = 0.f, acc_sy2 = 0.f;

    // ---- helper lambdas ----
    auto issue_chunk = [&](int chunk, unsigned sbuf, float* fbuf) {
        const int t0   = chunk * TT;
        const int vlen = min(TT, T_LEN - t0);
        #pragma unroll
        for (int p = 0; p < 8; ++p) {
            const int c = p * 16 + lrow;
            const unsigned dst = sbuf + (unsigned)(c * PITCH + 4 * lt4) * 4u;
            if (4 * lt4 < vlen) {
                cp_async16(dst, xb + (size_t)c * T_LEN + t0 + 4 * lt4);
            } else {
                *reinterpret_cast<float4*>(&fbuf[c * PITCH + 4 * lt4]) =
                    make_float4(0.f, 0.f, 0.f, 0.f);
            }
        }
        cp_commit();
    };

    auto compute_chunk = [&](int chunk, const float* tile) {
        const int t0   = chunk * TT;
        const int vlen = min(TT, T_LEN - t0);

        // colsum: group g sums 32 channels at time cs_t (serial LDS, lanes conflict-free)
        float csum = 0.f;
        const float* col = tile + (cs_g * 32) * PITCH + cs_t;
        #pragma unroll 8
        for (int c = 0; c < 32; ++c) csum += col[c * PITCH];
        part[cs_g * TT + cs_t] = csum;
        __syncthreads();

        // combine -> mrow, g_m  (first 64 threads)
        if (tid < TT) {
            float m = (part[tid] + part[TT + tid] + part[2 * TT + tid] + part[3 * TT + tid])
                      * (1.0f / 128.0f);
            mrow[tid] = m;
            if (tid < vlen) g_m[(size_t)b * T_LEN + t0 + tid] = m;
        }
        __syncthreads();

        // per-channel accumulation: (c, h) covers t in [h*32, h*32+32)
        const float* trow = tile + p2_c * PITCH + p2_h * 32;
        const float* mr   = mrow + p2_h * 32;
        #pragma unroll
        for (int tt = 0; tt < 32; tt += 4) {
            float4 v  = *reinterpret_cast<const float4*>(&trow[tt]);   // LDS.128, no conflicts
            float4 m4 = *reinterpret_cast<const float4*>(&mr[tt]);
            float a0 = v.x - m4.x, a1 = v.y - m4.y, a2 = v.z - m4.z, a3 = v.w - m4.w;
            acc_sy  += (a0 + a1) + (a2 + a3);          // zero-filled tail contributes 0
            acc_sy2 += a0 * a0 + a1 * a1 + a2 * a2 + a3 * a3;
        }
    };

    // ---- pipeline over chunks bx, bx+G, ... ----
    const int first = blockIdx.x;
    issue_chunk(first, s0, tile0);

    int k = first;
    int parity = 0;
    while (k < NCHUNK) {
        const int knext = k + GSTRIDE;
        if (knext < NCHUNK) {
            issue_chunk(knext, parity ? s0 : s1, parity ? tile0 : tile1);
            cp_wait<1>();               // chunk k's group is complete
        } else {
            cp_wait<0>();
        }
        __syncthreads();                // all loads/zero-fills of chunk k visible
        compute_chunk(k, parity ? tile1 : tile0);
        __syncthreads();                // buffer k reusable next round
        k = knext;
        parity ^= 1;
    }

    // final per-channel atomics (one pair per thread)
    atomicAdd(&g_sum [b * CH + p2_c], acc_sy);
    atomicAdd(&g_sum2[b * CH + p2_c], acc_sy2);
}

// ---------------------------------------------------------------- kernel 2: finalize + re-zero
__global__ void eeg_finalize_kernel() {
    int i = blockIdx.x * blockDim.x + threadIdx.x;
    if (i < BATCH * CH) {
        const float inv_t = 1.0f / (float)T_LEN;
        float mean = g_sum[i] * inv_t;
        float var  = g_sum2[i] * inv_t - mean * mean;
        float sd   = sqrtf(fmaxf(var, 0.f));
        g_mean[i] = mean;
        g_istd[i] = (sd == 0.f) ? 1.f : (1.f / sd);
        g_sum [i] = 0.f;       // reset for next graph replay (statically zero-init)
        g_sum2[i] = 0.f;
    }
}

// ---------------------------------------------------------------- kernel 3: normalize
// grid = (5, 8192): blockIdx.y = (b,c) pair. 2 float4 per thread, loads front-batched.
__global__ __launch_bounds__(256) void eeg_norm_kernel(const float4* __restrict__ x4,
                                                       float4* __restrict__ o4) {
    const int bc = blockIdx.y;
    const int b  = bc >> 7;
    const int ta = blockIdx.x * 512 + threadIdx.x;
    const int tb = ta + 256;

    const float mean = g_mean[bc];
    const float istd = g_istd[bc];

    const float4* __restrict__ xp = x4 + (size_t)bc * T4;
    float4*                   op = o4 + (size_t)bc * T4;
    const float4* __restrict__ mp =
        reinterpret_cast<const float4*>(g_m + (size_t)b * T_LEN);

    const bool va = ta < T4;
    const bool vb = tb < T4;

    float4 v0, v1, m0, m1;
    if (va) { v0 = xp[ta]; m0 = mp[ta]; }
    if (vb) { v1 = xp[tb]; m1 = mp[tb]; }

    if (va) {
        float4 r;
        r.x = (v0.x - m0.x - mean) * istd;
        r.y = (v0.y - m0.y - mean) * istd;
        r.z = (v0.z - m0.z - mean) * istd;
        r.w = (v0.w - m0.w - mean) * istd;
        op[ta] = r;
    }
    if (vb) {
        float4 r;
        r.x = (v1.x - m1.x - mean) * istd;
        r.y = (v1.y - m1.y - mean) * istd;
        r.z = (v1.z - m1.z - mean) * istd;
        r.w = (v1.w - m1.w - mean) * istd;
        op[tb] = r;
    }
}

// ---------------------------------------------------------------- launch
extern "C" void kernel_launch(void* const* d_in, const int* in_sizes, int n_in,
                              void* d_out, int out_size) {
    (void)in_sizes; (void)n_in; (void)out_size;
    const float* x = (const float*)d_in[0];
    float* out = (float*)d_out;

    static const size_t smem_bytes = (2 * CH * PITCH + 5 * TT) * sizeof(float); // ~70.9 KB
    cudaFuncSetAttribute(eeg_stats_kernel,
                         cudaFuncAttributeMaxDynamicSharedMemorySize,
                         (int)smem_bytes);

    // 1) pipelined stats (accumulators start zeroed; finalize re-zeroes them)
    dim3 sgrid(GSTRIDE, BATCH);                  // (6, 64) = 384 blocks
    eeg_stats_kernel<<<sgrid, 256, smem_bytes>>>(x);

    // 2) finalize mean / inv_std + reset accumulators
    eeg_finalize_kernel<<<(BATCH * CH + 255) / 256, 256>>>();

    // 3) normalize
    dim3 ngrid((T4 + 511) / 512, BATCH * CH);    // (5, 8192)
    eeg_norm_kernel<<<ngrid, 256>>>((const float4*)x, (float4*)out);
}

// round 11
// speedup vs baseline: 1.1919x; 1.0380x over previous
#include <cuda_runtime.h>
#include <cstdint>
#include <math.h>

// Problem constants: x is (64, 128, 10000) fp32.
#define BATCH 64
#define CH    128
#define T_LEN 10000
#define TT    32            // time-chunk per pipeline stage
#define PITCH 36            // floats; 144B rows: 16B-aligned, ≡4 mod 32 banks
#define NCHUNK 313          // ceil(10000/32); last chunk vlen=16
#define GSTRIDE 7           // grid (7,64) = 448 blocks ≈ 3/SM
#define NBUF  4             // pipeline depth
#define T4    (T_LEN / 4)   // 2500
#define TILE_FLOATS (CH * PITCH)

// Scratch (no allocations allowed). Statically zero-initialized.
__device__ float g_m[BATCH * T_LEN];      // mean over channels at each (b,t)
__device__ float g_sum [BATCH * CH];      // accumulator (reset by finalize)
__device__ float g_sum2[BATCH * CH];      // accumulator (reset by finalize)
__device__ float g_mean[BATCH * CH];
__device__ float g_istd[BATCH * CH];

__device__ __forceinline__ void cp_async16(unsigned sdst, const void* gsrc) {
    asm volatile("cp.async.cg.shared.global [%0], [%1], 16;\n"
                 :: "r"(sdst), "l"(gsrc));
}
__device__ __forceinline__ void cp_commit() {
    asm volatile("cp.async.commit_group;\n");
}
template <int N>
__device__ __forceinline__ void cp_wait() {
    asm volatile("cp.async.wait_group %0;\n" :: "n"(N));
}

// ---------------------------------------------------------------- kernel 1: 4-deep pipelined stats
// 256 threads/block. 3 chunks always in flight via cp.async; per-thread channel-stat
// accumulators live in registers across chunks; one atomicAdd pair per thread at end.
__global__ __launch_bounds__(256) void eeg_stats_kernel(const float* __restrict__ x) {
    extern __shared__ float s[];
    float* part = s + NBUF * TILE_FLOATS;      // 8 * TT  (per-group colsum partials)
    float* mrow = part + 8 * TT;               // TT      (channel mean per t)

    const int b   = blockIdx.y;
    const int tid = threadIdx.x;

    // cp.async issue mapping: 4 passes; thread covers (row = p*32 + tid>>3, slot = tid&7)
    const int irow  = tid >> 3;                // 0..31
    const int islot = tid & 7;                 // float4 slot (t = 4*islot)
    // colsum mapping: thread = (t = tid&31, group g = tid>>5 of 16 channels)
    const int cs_t = tid & 31;
    const int cs_g = tid >> 5;
    // phase-2 mapping (fixed per thread across all chunks)
    const int p2_c = tid & (CH - 1);
    const int p2_h = tid >> 7;                 // 0..1 -> t base h*16

    const float* __restrict__ xb = x + (size_t)b * CH * T_LEN;
    const unsigned sbase = (unsigned)__cvta_generic_to_shared(s);

    float acc_sy = 0.f, acc_sy2 = 0.f;

    auto issue_chunk = [&](int chunk, int buf) {
        if (chunk < NCHUNK) {
            const int t0   = chunk * TT;
            const int vlen = min(TT, T_LEN - t0);
            const unsigned sb = sbase + (unsigned)(buf * TILE_FLOATS) * 4u;
            float* fb = s + buf * TILE_FLOATS;
            #pragma unroll
            for (int p = 0; p < 4; ++p) {
                const int c = p * 32 + irow;
                const int toff = 4 * islot;
                if (toff < vlen) {
                    cp_async16(sb + (unsigned)(c * PITCH + toff) * 4u,
                               xb + (size_t)c * T_LEN + t0 + toff);
                } else {
                    *reinterpret_cast<float4*>(&fb[c * PITCH + toff]) =
                        make_float4(0.f, 0.f, 0.f, 0.f);
                }
            }
        }
        cp_commit();   // empty group when chunk invalid keeps wait-counts aligned
    };

    auto compute_chunk = [&](int chunk, const float* tile) {
        const int t0   = chunk * TT;
        const int vlen = min(TT, T_LEN - t0);

        // colsum: group g sums 16 channels at time cs_t (conflict-free scalar LDS)
        float csum = 0.f;
        const float* col = tile + (cs_g * 16) * PITCH + cs_t;
        #pragma unroll
        for (int c = 0; c < 16; ++c) csum += col[c * PITCH];
        part[cs_g * TT + cs_t] = csum;
        __syncthreads();

        // combine 8 partials -> mrow, g_m (first 32 threads)
        if (tid < TT) {
            float m = 0.f;
            #pragma unroll
            for (int g = 0; g < 8; ++g) m += part[g * TT + tid];
            m *= (1.0f / 128.0f);
            mrow[tid] = m;
            if (tid < vlen) g_m[(size_t)b * T_LEN + t0 + tid] = m;
        }
        __syncthreads();

        // per-channel accumulation: (c, h) covers t in [h*16, h*16+16) via LDS.128
        const float* trow = tile + p2_c * PITCH + p2_h * 16;
        const float* mr   = mrow + p2_h * 16;
        #pragma unroll
        for (int tt = 0; tt < 16; tt += 4) {
            float4 v  = *reinterpret_cast<const float4*>(&trow[tt]);
            float4 m4 = *reinterpret_cast<const float4*>(&mr[tt]);    // broadcast
            float a0 = v.x - m4.x, a1 = v.y - m4.y, a2 = v.z - m4.z, a3 = v.w - m4.w;
            acc_sy  += (a0 + a1) + (a2 + a3);          // zero-filled tail contributes 0
            acc_sy2 += a0 * a0 + a1 * a1 + a2 * a2 + a3 * a3;
        }
    };

    // ---- pipeline: 3 chunks in flight ----
    const int first = blockIdx.x;
    int issue_k = first;
    #pragma unroll
    for (int d = 0; d < NBUF - 1; ++d) {       // prologue: buffers 0,1,2
        issue_chunk(issue_k, d);
        issue_k += GSTRIDE;
    }

    int bufidx = 0;
    for (int k = first; k < NCHUNK; k += GSTRIDE) {
        issue_chunk(issue_k, (bufidx + NBUF - 1) & (NBUF - 1));
        issue_k += GSTRIDE;
        cp_wait<NBUF - 1>();            // chunk k's group complete
        __syncthreads();                // its STS (and any zero-fills) visible to all
        compute_chunk(k, s + bufidx * TILE_FLOATS);
        __syncthreads();                // buffer reusable for next issue
        bufidx = (bufidx + 1) & (NBUF - 1);
    }

    // final per-channel atomics (one pair per thread)
    atomicAdd(&g_sum [b * CH + p2_c], acc_sy);
    atomicAdd(&g_sum2[b * CH + p2_c], acc_sy2);
}

// ---------------------------------------------------------------- kernel 2: finalize + re-zero
__global__ void eeg_finalize_kernel() {
    int i = blockIdx.x * blockDim.x + threadIdx.x;
    if (i < BATCH * CH) {
        const float inv_t = 1.0f / (float)T_LEN;
        float mean = g_sum[i] * inv_t;
        float var  = g_sum2[i] * inv_t - mean * mean;
        float sd   = sqrtf(fmaxf(var, 0.f));
        g_mean[i] = mean;
        g_istd[i] = (sd == 0.f) ? 1.f : (1.f / sd);
        g_sum [i] = 0.f;       // reset for next graph replay (statically zero-init)
        g_sum2[i] = 0.f;
    }
}

// ---------------------------------------------------------------- kernel 3: normalize
// grid = (5, 8192): blockIdx.y = (b,c) pair. 2 float4 per thread, loads front-batched.
__global__ __launch_bounds__(256) void eeg_norm_kernel(const float4* __restrict__ x4,
                                                       float4* __restrict__ o4) {
    const int bc = blockIdx.y;
    const int b  = bc >> 7;
    const int ta = blockIdx.x * 512 + threadIdx.x;
    const int tb = ta + 256;

    const float mean = g_mean[bc];
    const float istd = g_istd[bc];

    const float4* __restrict__ xp = x4 + (size_t)bc * T4;
    float4*                   op = o4 + (size_t)bc * T4;
    const float4* __restrict__ mp =
        reinterpret_cast<const float4*>(g_m + (size_t)b * T_LEN);

    const bool va = ta < T4;
    const bool vb = tb < T4;

    float4 v0, v1, m0, m1;
    if (va) { v0 = xp[ta]; m0 = mp[ta]; }
    if (vb) { v1 = xp[tb]; m1 = mp[tb]; }

    if (va) {
        float4 r;
        r.x = (v0.x - m0.x - mean) * istd;
        r.y = (v0.y - m0.y - mean) * istd;
        r.z = (v0.z - m0.z - mean) * istd;
        r.w = (v0.w - m0.w - mean) * istd;
        op[ta] = r;
    }
    if (vb) {
        float4 r;
        r.x = (v1.x - m1.x - mean) * istd;
        r.y = (v1.y - m1.y - mean) * istd;
        r.z = (v1.z - m1.z - mean) * istd;
        r.w = (v1.w - m1.w - mean) * istd;
        op[tb] = r;
    }
}

// ---------------------------------------------------------------- launch
extern "C" void kernel_launch(void* const* d_in, const int* in_sizes, int n_in,
                              void* d_out, int out_size) {
    (void)in_sizes; (void)n_in; (void)out_size;
    const float* x = (const float*)d_in[0];
    float* out = (float*)d_out;

    static const size_t smem_bytes =
        (NBUF * TILE_FLOATS + 9 * TT) * sizeof(float);   // ~73.3 KB -> 3 blocks/SM
    cudaFuncSetAttribute(eeg_stats_kernel,
                         cudaFuncAttributeMaxDynamicSharedMemorySize,
                         (int)smem_bytes);

    // 1) pipelined stats (accumulators start zeroed; finalize re-zeroes them)
    dim3 sgrid(GSTRIDE, BATCH);                  // (7, 64) = 448 blocks
    eeg_stats_kernel<<<sgrid, 256, smem_bytes>>>(x);

    // 2) finalize mean / inv_std + reset accumulators
    eeg_finalize_kernel<<<(BATCH * CH + 255) / 256, 256>>>();

    // 3) normalize
    dim3 ngrid((T4 + 511) / 512, BATCH * CH);    // (5, 8192)
    eeg_norm_kernel<<<ngrid, 256>>>((const float4*)x, (float4*)out);
}